// round 17
// baseline (speedup 1.0000x reference)
#include <cuda_runtime.h>
#include <cuda_bf16.h>
#include <cuda_fp16.h>
#include <cstdint>

#define NN   100000
#define DD   128
#define EE   800000
#define NET  2
#define TM   128
#define LN_EPS 1e-5f

#define XS 136          // fp16 row stride (272B -> conflict-free ldmatrix)

// ---- smem byte offsets (transform): 114,176 B -> 2 CTAs/SM ----
#define OFF_XH 0            // feat hi (fp16)
#define OFF_B0 34816        // WcK, then K stage
#define OFF_B1 69632        // WcQ, then WcV
#define OFF_SC 104448       // 128*16 fp32 = 8KB
#define OFF_BI 112640       // 384 fp32 = 1536B
#define SMEM_BYTES 114176

// ---- scratch (device globals) ----
__device__ __nv_bfloat16 g_Whb[(size_t)NET * NN * DD];   // bf16 messages
__device__ __half g_Wc[NET * 3 * DD * DD];               // composite fp16 weights
__device__ float g_bias[NET * 3 * DD];                   // composite biases
__device__ int g_cnt[NET * NN];
__device__ int g_off[NET * NN + 1];
__device__ int g_cur[NET * NN];
__device__ int g_bsum[256];
__device__ int g_sorted[NET * EE];

// ---- warp MMA primitives ----
__device__ __forceinline__ void ldmat4(uint32_t* r, uint32_t addr) {
    asm volatile("ldmatrix.sync.aligned.m8n8.x4.shared.b16 {%0,%1,%2,%3}, [%4];"
        : "=r"(r[0]), "=r"(r[1]), "=r"(r[2]), "=r"(r[3]) : "r"(addr));
}
__device__ __forceinline__ void ldmat4t(uint32_t* r, uint32_t addr) {
    asm volatile("ldmatrix.sync.aligned.m8n8.x4.trans.shared.b16 {%0,%1,%2,%3}, [%4];"
        : "=r"(r[0]), "=r"(r[1]), "=r"(r[2]), "=r"(r[3]) : "r"(addr));
}
__device__ __forceinline__ void mma16816(float* c, const uint32_t* a, const uint32_t* b) {
    asm volatile("mma.sync.aligned.m16n8k16.row.col.f32.f16.f16.f32 "
        "{%0,%1,%2,%3}, {%4,%5,%6,%7}, {%8,%9}, {%0,%1,%2,%3};"
        : "+f"(c[0]), "+f"(c[1]), "+f"(c[2]), "+f"(c[3])
        : "r"(a[0]), "r"(a[1]), "r"(a[2]), "r"(a[3]), "r"(b[0]), "r"(b[1]));
}
#define CP_COMMIT() asm volatile("cp.async.commit_group;" ::: "memory")
#define CP_WAIT(n)  asm volatile("cp.async.wait_group %0;" :: "n"(n) : "memory")

__device__ __forceinline__ void cpw(uint32_t sb, int offW, const __half* __restrict__ gsrc, int t) {
#pragma unroll
    for (int i = 0; i < 8; i++) {
        int u = i * 256 + t;
        int k = u >> 4, n16 = u & 15;
        uint32_t dh = sb + offW + k * (XS * 2) + n16 * 16;
        const char* gh = (const char*)gsrc + k * 256 + n16 * 16;
        asm volatile("cp.async.cg.shared.global [%0], [%1], 16;" :: "r"(dh), "l"(gh));
    }
}

// fp16 GEMM, warp tile M16 x N128, hi-only
__device__ __forceinline__ void wgemm(char* smem, float acc[16][4], int offW, int w, int lane) {
    const int r = lane & 7, sel = lane >> 3;
    const int rowoff = (sel & 1) ? 8 : 0;
    const int coloff = (sel & 2) ? 8 : 0;
    const uint32_t sb = (uint32_t)__cvta_generic_to_shared(smem);
    const int arow = 16 * w + r + rowoff;
    const uint32_t axh = sb + OFF_XH + (uint32_t)(arow * XS + coloff) * 2;
#pragma unroll
    for (int kk = 0; kk < 8; kk++) {
        uint32_t Ah[4];
        ldmat4(Ah, axh + kk * 32);
        const int brow = kk * 16 + r + rowoff;
        const uint32_t bh = sb + offW + (uint32_t)(brow * XS + coloff) * 2;
#pragma unroll
        for (int nt16 = 0; nt16 < 8; nt16++) {
            uint32_t Bh[4];
            ldmat4t(Bh, bh + nt16 * 32);
            mma16816(acc[2 * nt16],     Ah, Bh);
            mma16816(acc[2 * nt16 + 1], Ah, Bh + 2);
        }
    }
}

__device__ __forceinline__ void zacc(float acc[16][4]) {
#pragma unroll
    for (int i = 0; i < 16; i++) { acc[i][0] = acc[i][1] = acc[i][2] = acc[i][3] = 0.f; }
}

// ---- composite weight prep (fused bias) ----
__global__ void __launch_bounds__(256) wprep_kernel(
    const float* __restrict__ Wt, const float* __restrict__ bt,
    const float* __restrict__ Kw, const float* __restrict__ Kb,
    const float* __restrict__ Qw, const float* __restrict__ Qb,
    const float* __restrict__ Vw, const float* __restrict__ Vb)
{
    int q = blockIdx.x & 3, mat = blockIdx.x >> 2;
    int e = blockIdx.y;
    const float* srcs[3] = {Kw, Qw, Vw};
    const float* bsrc[3] = {Kb, Qb, Vb};
    const float* A = Wt + (size_t)e * 16384;
    const float* B = srcs[mat] + (size_t)e * 16384;
    extern __shared__ float s[];
    float* sA = s;
    float* sB = s + 16384;
    int t = threadIdx.x;
    for (int i = t; i < 4096; i += 256) ((float4*)sA)[i] = ((const float4*)A)[i];
    for (int i = t; i < 1024; i += 256) {
        int j = i >> 3, cc = (i & 7) * 4;
        *(float4*)(sB + j * 32 + cc) = *(const float4*)(B + (size_t)j * 128 + q * 32 + cc);
    }
    __syncthreads();
    int r0 = (t >> 2) * 2, c0 = (t & 3) * 8;
    float acc0[8] = {0,0,0,0,0,0,0,0}, acc1[8] = {0,0,0,0,0,0,0,0};
    for (int j = 0; j < 128; j++) {
        float a0 = sA[r0 * 128 + j], a1 = sA[(r0 + 1) * 128 + j];
        float4 b0 = *(float4*)(sB + j * 32 + c0);
        float4 b1 = *(float4*)(sB + j * 32 + c0 + 4);
        acc0[0] += a0 * b0.x; acc0[1] += a0 * b0.y; acc0[2] += a0 * b0.z; acc0[3] += a0 * b0.w;
        acc0[4] += a0 * b1.x; acc0[5] += a0 * b1.y; acc0[6] += a0 * b1.z; acc0[7] += a0 * b1.w;
        acc1[0] += a1 * b0.x; acc1[1] += a1 * b0.y; acc1[2] += a1 * b0.z; acc1[3] += a1 * b0.w;
        acc1[4] += a1 * b1.x; acc1[5] += a1 * b1.y; acc1[6] += a1 * b1.z; acc1[7] += a1 * b1.w;
    }
    __half* C = g_Wc + (size_t)(e * 3 + mat) * 16384;
#pragma unroll
    for (int cc = 0; cc < 8; cc += 2) {
        __half2 p0 = __floats2half2_rn(acc0[cc], acc0[cc + 1]);
        __half2 p1 = __floats2half2_rn(acc1[cc], acc1[cc + 1]);
        *(uint32_t*)(C + (size_t)r0 * 128 + q * 32 + c0 + cc) = *(uint32_t*)&p0;
        *(uint32_t*)(C + (size_t)(r0 + 1) * 128 + q * 32 + c0 + cc) = *(uint32_t*)&p1;
    }
    if (t < 32) {
        int col = q * 32 + t;
        float sv = bsrc[mat][e * 128 + col];
        for (int j = 0; j < 128; j++) sv += bt[e * 128 + j] * sB[j * 32 + t];
        g_bias[(e * 3 + mat) * 128 + col] = sv;
    }
}

// ================= fused transform: K,Q,V from feat (2 CTAs/SM) =================
__global__ void __launch_bounds__(256, 2) transform_kernel(const float* __restrict__ feat)
{
    extern __shared__ char smem[];
    const uint32_t sb = (uint32_t)__cvta_generic_to_shared(smem);
    const int e    = blockIdx.y;
    const int base = blockIdx.x * TM;
    const int t    = threadIdx.x;
    const int w = t >> 5, lane = t & 31;
    const int g = lane >> 2, c = lane & 3;
    const int R0 = 16 * w + g, R1 = R0 + 8;
    float* sScf = (float*)(smem + OFF_SC);
    float* sBI  = (float*)(smem + OFF_BI);
    const __half* Wb = g_Wc + (size_t)e * 3 * 16384;

    cpw(sb, OFF_B0, Wb,         t); CP_COMMIT();   // WcK
    cpw(sb, OFF_B1, Wb + 16384, t); CP_COMMIT();   // WcQ

    if (t < 128) {
        sBI[t]       = g_bias[(e * 3 + 0) * 128 + t];
        sBI[128 + t] = g_bias[(e * 3 + 1) * 128 + t];
        sBI[256 + t] = g_bias[(e * 3 + 2) * 128 + t];
    }

    // feat -> XH (fp16 hi only)
#pragma unroll
    for (int i = 0; i < 16; i++) {
        int u = i * 256 + t;
        int m = u >> 5, k = (u & 31) * 4;
        int node = base + m;
        float4 v = make_float4(0.f, 0.f, 0.f, 0.f);
        if (node < NN) v = *(const float4*)(feat + (size_t)node * DD + k);
        __half2 h0 = __floats2half2_rn(v.x, v.y);
        __half2 h1 = __floats2half2_rn(v.z, v.w);
        uint2 hv;
        hv.x = *(uint32_t*)&h0; hv.y = *(uint32_t*)&h1;
        *(uint2*)(smem + OFF_XH + ((size_t)m * XS + k) * 2) = hv;
    }
    CP_WAIT(1);                                    // WcK ready
    __syncthreads();

    float acc[16][4];

    // ---- GEMM K ----
    zacc(acc);
    wgemm(smem, acc, OFF_B0, w, lane);
    __syncthreads();                               // B0 reads done

    // stage K (+bK) -> B0
#pragma unroll
    for (int nt = 0; nt < 16; nt++) {
        int col = nt * 8 + 2 * c;
        float bx = sBI[col], by = sBI[col + 1];
        __half2 p0 = __floats2half2_rn(acc[nt][0] + bx, acc[nt][1] + by);
        __half2 p1 = __floats2half2_rn(acc[nt][2] + bx, acc[nt][3] + by);
        *(uint32_t*)(smem + OFF_B0 + ((size_t)R0 * XS + col) * 2) = *(uint32_t*)&p0;
        *(uint32_t*)(smem + OFF_B0 + ((size_t)R1 * XS + col) * 2) = *(uint32_t*)&p1;
    }
    CP_WAIT(0);                                    // WcQ ready
    __syncthreads();

    // ---- GEMM Q ----
    zacc(acc);
    wgemm(smem, acc, OFF_B1, w, lane);
    __syncthreads();                               // B1 reads done
    cpw(sb, OFF_B1, Wb + 2 * 16384, t); CP_COMMIT();   // WcV

#pragma unroll
    for (int nt = 0; nt < 16; nt++) {
        int col = nt * 8 + 2 * c;
        float bx = sBI[128 + col], by = sBI[128 + col + 1];
        acc[nt][0] += bx; acc[nt][1] += by;
        acc[nt][2] += bx; acc[nt][3] += by;
    }

    // ---- scores ----
    const float scale = 0.17677669529663687f;
#pragma unroll
    for (int gp = 0; gp < 4; gp++) {
        float2 kv0[4], kv1[4];
#pragma unroll
        for (int j = 0; j < 4; j++) {
            __half2 k0 = *(const __half2*)(smem + OFF_B0 + ((size_t)R0 * XS + gp * 32 + j * 8 + 2 * c) * 2);
            __half2 k1 = *(const __half2*)(smem + OFF_B0 + ((size_t)R1 * XS + gp * 32 + j * 8 + 2 * c) * 2);
            kv0[j] = __half22float2(k0);
            kv1[j] = __half22float2(k1);
        }
#pragma unroll
        for (int h = 0; h < 4; h++) {
            float p0 = 0.f, p1 = 0.f;
#pragma unroll
            for (int j = 0; j < 4; j++) {
                p0 += acc[4 * h + j][0] * kv0[j].x + acc[4 * h + j][1] * kv0[j].y;
                p1 += acc[4 * h + j][2] * kv1[j].x + acc[4 * h + j][3] * kv1[j].y;
            }
            p0 += __shfl_xor_sync(0xffffffffu, p0, 1);
            p0 += __shfl_xor_sync(0xffffffffu, p0, 2);
            p1 += __shfl_xor_sync(0xffffffffu, p1, 1);
            p1 += __shfl_xor_sync(0xffffffffu, p1, 2);
            if (c == 0) {
                sScf[R0 * 16 + h * 4 + gp] = p0 * scale;
                sScf[R1 * 16 + h * 4 + gp] = p1 * scale;
            }
        }
    }
    __syncthreads();

    // ---- softmax ----
#pragma unroll
    for (int i = 0; i < 2; i++) {
        int p = t * 2 + i;
        int row = p >> 2, h = p & 3;
        float4 s = *(float4*)(sScf + row * 16 + h * 4);
        float m = fmaxf(fmaxf(s.x, s.y), fmaxf(s.z, s.w));
        float e0 = __expf(s.x - m), e1 = __expf(s.y - m), e2 = __expf(s.z - m), e3 = __expf(s.w - m);
        float inv = 1.f / (e0 + e1 + e2 + e3);
        *(float4*)(sScf + row * 16 + h * 4) = make_float4(e0 * inv, e1 * inv, e2 * inv, e3 * inv);
    }
    CP_WAIT(0);                                    // WcV ready
    __syncthreads();

    // ---- GEMM V ----
    zacc(acc);
    wgemm(smem, acc, OFF_B1, w, lane);
#pragma unroll
    for (int nt = 0; nt < 16; nt++) {
        int col = nt * 8 + 2 * c;
        float bx = sBI[256 + col], by = sBI[256 + col + 1];
        acc[nt][0] += bx; acc[nt][1] += by;
        acc[nt][2] += bx; acc[nt][3] += by;
    }

    // ---- combine -> g_Whb (bf16) ----
    const int n0 = base + R0, n1 = base + R1;
    __nv_bfloat16* op0 = g_Whb + ((size_t)e * NN + n0) * DD;
    __nv_bfloat16* op1 = g_Whb + ((size_t)e * NN + n1) * DD;
#pragma unroll
    for (int h = 0; h < 4; h++) {
        float4 a0 = *(float4*)(sScf + R0 * 16 + 4 * h);
        float4 a1 = *(float4*)(sScf + R1 * 16 + 4 * h);
#pragma unroll
        for (int j3 = 0; j3 < 4; j3++) {
            int col = (h * 4 + j3) * 8 + 2 * c;
            float o00 = a0.x * acc[j3][0]      + a0.y * acc[4 + j3][0]
                      + a0.z * acc[8 + j3][0]  + a0.w * acc[12 + j3][0];
            float o01 = a0.x * acc[j3][1]      + a0.y * acc[4 + j3][1]
                      + a0.z * acc[8 + j3][1]  + a0.w * acc[12 + j3][1];
            float o10 = a1.x * acc[j3][2]      + a1.y * acc[4 + j3][2]
                      + a1.z * acc[8 + j3][2]  + a1.w * acc[12 + j3][2];
            float o11 = a1.x * acc[j3][3]      + a1.y * acc[4 + j3][3]
                      + a1.z * acc[8 + j3][3]  + a1.w * acc[12 + j3][3];
            if (n0 < NN) {
                __nv_bfloat162 pk = __floats2bfloat162_rn(o00, o01);
                *(uint32_t*)(op0 + col) = *(uint32_t*)&pk;
            }
            if (n1 < NN) {
                __nv_bfloat162 pk = __floats2bfloat162_rn(o10, o11);
                *(uint32_t*)(op1 + col) = *(uint32_t*)&pk;
            }
        }
    }
}

// ================= CSR build =================
__global__ void cnt_zero_kernel() {
    int i = blockIdx.x * 1024 + threadIdx.x;
    if (i < NET * NN) g_cnt[i] = 0;
}
__global__ void cnt_kernel(const int* __restrict__ dst) {
    int e = blockIdx.y;
    int i = blockIdx.x * blockDim.x + threadIdx.x;
    if (i < EE) atomicAdd(&g_cnt[e * NN + dst[(size_t)e * EE + i]], 1);
}
__global__ void scan_a_kernel() {
    __shared__ int wsum[32];
    int t = threadIdx.x, lane = t & 31, wid = t >> 5;
    int gid = blockIdx.x * 1024 + t;
    int v = (gid < NET * NN) ? g_cnt[gid] : 0;
    int x = v;
#pragma unroll
    for (int o = 1; o < 32; o <<= 1) { int y = __shfl_up_sync(0xffffffffu, x, o); if (lane >= o) x += y; }
    if (lane == 31) wsum[wid] = x;
    __syncthreads();
    if (wid == 0) {
        int s = wsum[lane];
#pragma unroll
        for (int o = 1; o < 32; o <<= 1) { int y = __shfl_up_sync(0xffffffffu, s, o); if (lane >= o) s += y; }
        wsum[lane] = s;
    }
    __syncthreads();
    int pfx = wid ? wsum[wid - 1] : 0;
    if (gid < NET * NN) g_off[gid] = pfx + x - v;
    if (t == 1023) g_bsum[blockIdx.x] = pfx + x;
}
__global__ void scan_b_kernel() {
    __shared__ int wsum[8];
    int t = threadIdx.x, lane = t & 31, wid = t >> 5;
    int v = (t < 196) ? g_bsum[t] : 0;
    int x = v;
#pragma unroll
    for (int o = 1; o < 32; o <<= 1) { int y = __shfl_up_sync(0xffffffffu, x, o); if (lane >= o) x += y; }
    if (lane == 31) wsum[wid] = x;
    __syncthreads();
    if (t == 0) {
        int run = 0;
#pragma unroll
        for (int i = 0; i < 8; i++) { int tmp = wsum[i]; wsum[i] = run; run += tmp; }
    }
    __syncthreads();
    if (t < 196) g_bsum[t] = wsum[wid] + x - v;
}
__global__ void scan_c_kernel() {
    int gid = blockIdx.x * 1024 + threadIdx.x;
    if (gid < NET * NN) {
        int o = g_off[gid] + g_bsum[gid >> 10];
        g_off[gid] = o;
        g_cur[gid] = o;
    }
    if (gid == 0) g_off[NET * NN] = NET * EE;
}
__global__ void fill_kernel(const int* __restrict__ src, const int* __restrict__ dst) {
    int e = blockIdx.y;
    int i = blockIdx.x * blockDim.x + threadIdx.x;
    if (i < EE) {
        int d = dst[(size_t)e * EE + i];
        int pos = atomicAdd(&g_cur[e * NN + d], 1);
        g_sorted[pos] = src[(size_t)e * EE + i];
    }
}

// ======== fused gather: 2 warps per node (one per etype) + residual + LayerNorm ========
// block = 256 threads = 8 warps = 4 nodes. warp pair (2k, 2k+1) -> node, etype = wid&1.
__global__ void __launch_bounds__(256) gather_ln_kernel(
    const float* __restrict__ feat,
    const float* __restrict__ ln_g, const float* __restrict__ ln_b,
    float* __restrict__ out)
{
    __shared__ float sPart[4][128];      // etype-1 partials
    int wid  = threadIdx.x >> 5;
    int lane = threadIdx.x & 31;
    int nl   = wid >> 1;                 // node slot in block (0..3)
    int e    = wid & 1;
    int w    = blockIdx.x * 4 + nl;
    bool valid = (w < NN);

    float t0 = 0.f, t1 = 0.f, t2 = 0.f, t3 = 0.f;
    float inv = 1.f;
    if (valid) {
        int beg = g_off[e * NN + w], end = g_off[e * NN + w + 1];
        const __nv_bfloat16* WhE = g_Whb + (size_t)e * NN * DD + lane * 4;
        int i = beg;
        for (; i + 8 <= end; i += 8) {
            int sx[8];
#pragma unroll
            for (int u = 0; u < 8; u++) sx[u] = __ldg(&g_sorted[i + u]);
            uint2 uu[8];
#pragma unroll
            for (int u = 0; u < 8; u++) uu[u] = *(const uint2*)(WhE + (size_t)sx[u] * DD);
#pragma unroll
            for (int u = 0; u < 8; u++) {
                float2 p0 = __bfloat1622float2(*(__nv_bfloat162*)&uu[u].x);
                float2 p1 = __bfloat1622float2(*(__nv_bfloat162*)&uu[u].y);
                t0 += p0.x; t1 += p0.y; t2 += p1.x; t3 += p1.y;
            }
        }
        for (; i + 2 <= end; i += 2) {
            int s0 = __ldg(&g_sorted[i]), s1 = __ldg(&g_sorted[i + 1]);
            uint2 u0 = *(const uint2*)(WhE + (size_t)s0 * DD);
            uint2 u1 = *(const uint2*)(WhE + (size_t)s1 * DD);
            float2 p0 = __bfloat1622float2(*(__nv_bfloat162*)&u0.x);
            float2 p1 = __bfloat1622float2(*(__nv_bfloat162*)&u0.y);
            float2 q0 = __bfloat1622float2(*(__nv_bfloat162*)&u1.x);
            float2 q1 = __bfloat1622float2(*(__nv_bfloat162*)&u1.y);
            t0 += p0.x + q0.x; t1 += p0.y + q0.y;
            t2 += p1.x + q1.x; t3 += p1.y + q1.y;
        }
        if (i < end) {
            int s0 = __ldg(&g_sorted[i]);
            uint2 u0 = *(const uint2*)(WhE + (size_t)s0 * DD);
            float2 p0 = __bfloat1622float2(*(__nv_bfloat162*)&u0.x);
            float2 p1 = __bfloat1622float2(*(__nv_bfloat162*)&u0.y);
            t0 += p0.x; t1 += p0.y; t2 += p1.x; t3 += p1.y;
        }
        inv = 1.f / fmaxf((float)(end - beg), 1.f);
    }
    t0 *= inv; t1 *= inv; t2 *= inv; t3 *= inv;

    if (e == 1) {
        float4 pv = make_float4(t0, t1, t2, t3);
        *(float4*)&sPart[nl][lane * 4] = pv;
    }
    __syncthreads();

    if (e == 0 && valid) {
        float4 p1 = *(float4*)&sPart[nl][lane * 4];
        float4 f = ((const float4*)(feat + (size_t)w * DD))[lane];
        float4 h = make_float4(t0 + p1.x + f.x, t1 + p1.y + f.y,
                               t2 + p1.z + f.z, t3 + p1.w + f.w);

        float s = h.x + h.y + h.z + h.w;
#pragma unroll
        for (int o = 16; o; o >>= 1) s += __shfl_xor_sync(0xffffffffu, s, o);
        float mu = s * (1.0f / 128.0f);

        float dx = h.x - mu, dy = h.y - mu, dz = h.z - mu, dw = h.w - mu;
        float q = dx * dx + dy * dy + dz * dz + dw * dw;
#pragma unroll
        for (int o = 16; o; o >>= 1) q += __shfl_xor_sync(0xffffffffu, q, o);
        float invs = rsqrtf(q * (1.0f / 128.0f) + LN_EPS);

        float4 gg = ((const float4*)ln_g)[lane];
        float4 bb = ((const float4*)ln_b)[lane];
        float4 o4 = make_float4(dx * invs * gg.x + bb.x, dy * invs * gg.y + bb.y,
                                dz * invs * gg.z + bb.z, dw * invs * gg.w + bb.w);
        ((float4*)out)[(size_t)w * 32 + lane] = o4;
    }
}

extern "C" void kernel_launch(void* const* d_in, const int* in_sizes, int n_in,
                              void* d_out, int out_size) {
    const float* feat = (const float*)d_in[0];
    const int*   src  = (const int*)d_in[1];
    const int*   dst  = (const int*)d_in[2];
    const float* Wt   = (const float*)d_in[3];
    const float* bt   = (const float*)d_in[4];
    const float* Kw   = (const float*)d_in[5];
    const float* Kb   = (const float*)d_in[6];
    const float* Qw   = (const float*)d_in[7];
    const float* Qb   = (const float*)d_in[8];
    const float* Vw   = (const float*)d_in[9];
    const float* Vb   = (const float*)d_in[10];
    const float* ln_g = (const float*)d_in[11];
    const float* ln_b = (const float*)d_in[12];
    float* out = (float*)d_out;

    cudaFuncSetAttribute(transform_kernel, cudaFuncAttributeMaxDynamicSharedMemorySize, SMEM_BYTES);
    cudaFuncSetAttribute(wprep_kernel, cudaFuncAttributeMaxDynamicSharedMemorySize, 81920);

    // Streams/events created ONCE on the first (non-captured) call; reused during
    // capture so the capture call is allocation-free.
    static cudaStream_t sA = nullptr, sB = nullptr;
    static cudaEvent_t evF = nullptr, evA = nullptr, evB = nullptr;
    if (sA == nullptr) {
        cudaStreamCreateWithFlags(&sA, cudaStreamNonBlocking);
        cudaStreamCreateWithFlags(&sB, cudaStreamNonBlocking);
        cudaEventCreateWithFlags(&evF, cudaEventDisableTiming);
        cudaEventCreateWithFlags(&evA, cudaEventDisableTiming);
        cudaEventCreateWithFlags(&evB, cudaEventDisableTiming);
        cnt_zero_kernel<<<1, 32, 0, sA>>>();   // materialize stream pools now
        cnt_zero_kernel<<<1, 32, 0, sB>>>();
    }

    cudaEventRecord(evF, 0);
    cudaStreamWaitEvent(sA, evF, 0);
    cudaStreamWaitEvent(sB, evF, 0);

    // Branch A: CSR build
    cnt_zero_kernel<<<196, 1024, 0, sA>>>();
    cnt_kernel<<<dim3(EE / 256, NET), 256, 0, sA>>>(dst);
    scan_a_kernel<<<196, 1024, 0, sA>>>();
    scan_b_kernel<<<1, 256, 0, sA>>>();
    scan_c_kernel<<<196, 1024, 0, sA>>>();
    fill_kernel<<<dim3(EE / 256, NET), 256, 0, sA>>>(src, dst);
    cudaEventRecord(evA, sA);

    // Branch B: weight prep + transform
    wprep_kernel<<<dim3(12, NET), 256, 81920, sB>>>(Wt, bt, Kw, Kb, Qw, Qb, Vw, Vb);
    transform_kernel<<<dim3((NN + TM - 1) / TM, NET), 256, SMEM_BYTES, sB>>>(feat);
    cudaEventRecord(evB, sB);

    // Join, then gather (2 warps/node) + LayerNorm
    cudaStreamWaitEvent(0, evA, 0);
    cudaStreamWaitEvent(0, evB, 0);
    gather_ln_kernel<<<(NN + 3) / 4, 256>>>(feat, ln_g, ln_b, out);
}